// round 4
// baseline (speedup 1.0000x reference)
#include <cuda_runtime.h>
#include <math.h>
#include <stdint.h>

#define N_NODES 50000
#define N_EDGES 800000
#define H 128
#define LN_EPS 1e-5f

#define AS_STRIDE 132
#define BS_STRIDE 136
#define SMEM_EDGE ((64 * AS_STRIDE + 128 * BS_STRIDE) * 4)

// Static device scratch (allowed; no runtime allocation)
__device__ float g_PQ[(size_t)N_NODES * 256];        // P | Q per node
__device__ float g_msg[(size_t)N_EDGES * H];         // messages, receiver-sorted slots
__device__ int   g_perm[N_EDGES];                    // slot -> original edge id
__device__ int   g_count[N_NODES];
__device__ int   g_off[N_NODES];
__device__ int   g_cursor[N_NODES];

__device__ __forceinline__ float tf32r(float x) {
    uint32_t u;
    asm("cvt.rna.tf32.f32 %0, %1;" : "=r"(u) : "f"(x));
    return __uint_as_float(u);
}

__device__ __forceinline__ void mma_tf32(float d[4], uint32_t a0, uint32_t a1,
                                         uint32_t a2, uint32_t a3,
                                         uint32_t b0, uint32_t b1) {
    asm volatile(
        "mma.sync.aligned.m16n8k8.row.col.f32.tf32.tf32.f32 "
        "{%0,%1,%2,%3}, {%4,%5,%6,%7}, {%8,%9}, {%0,%1,%2,%3};"
        : "+f"(d[0]), "+f"(d[1]), "+f"(d[2]), "+f"(d[3])
        : "r"(a0), "r"(a1), "r"(a2), "r"(a3), "r"(b0), "r"(b1));
}

// ---------------------------------------------------------------------------
// CSR build
// ---------------------------------------------------------------------------
__global__ void zero_count_kernel() {
    int i = blockIdx.x * blockDim.x + threadIdx.x;
    if (i < N_NODES) g_count[i] = 0;
}

__global__ void hist_kernel(const int* __restrict__ receivers) {
    int i = blockIdx.x * blockDim.x + threadIdx.x;
    if (i < N_EDGES) atomicAdd(&g_count[receivers[i]], 1);
}

// Single block, 1024 threads, chunk of 50 nodes per thread (two-pass, no reg array)
__global__ __launch_bounds__(1024) void scan_kernel() {
    __shared__ int warp_sums[32];
    const int t = threadIdx.x;
    const int lane = t & 31, warp = t >> 5;
    const int base = t * 50;

    int s = 0;
    for (int i = 0; i < 50; ++i) {
        int idx = base + i;
        if (idx < N_NODES) s += g_count[idx];
    }
    int v = s;
#pragma unroll
    for (int off = 1; off < 32; off <<= 1) {
        int n = __shfl_up_sync(0xffffffffu, v, off);
        if (lane >= off) v += n;
    }
    if (lane == 31) warp_sums[warp] = v;
    __syncthreads();
    if (warp == 0) {
        int w = warp_sums[lane];
#pragma unroll
        for (int off = 1; off < 32; off <<= 1) {
            int n = __shfl_up_sync(0xffffffffu, w, off);
            if (lane >= off) w += n;
        }
        warp_sums[lane] = w;
    }
    __syncthreads();
    int excl = (warp == 0 ? 0 : warp_sums[warp - 1]) + (v - s);
    for (int i = 0; i < 50; ++i) {
        int idx = base + i;
        if (idx < N_NODES) {
            g_off[idx] = excl;
            g_cursor[idx] = excl;
            excl += g_count[idx];
        }
    }
}

__global__ void scatter_kernel(const int* __restrict__ receivers) {
    int i = blockIdx.x * blockDim.x + threadIdx.x;
    if (i < N_EDGES) {
        int pos = atomicAdd(&g_cursor[receivers[i]], 1);
        g_perm[pos] = i;
    }
}

// ---------------------------------------------------------------------------
// Node projection: P = x@Ws + b1 (half 0), Q = x@Wr (half 1)
// ---------------------------------------------------------------------------
__global__ __launch_bounds__(256) void proj_kernel(const float* __restrict__ x,
                                                   const float* __restrict__ W1,
                                                   const float* __restrict__ b1) {
    __shared__ float As[128 * 64];
    __shared__ float Bs[32 * 128];

    const int tid  = threadIdx.x;
    const int half = blockIdx.y;
    const int m0   = blockIdx.x * 64;
    const int eg   = tid >> 5;
    const int og   = tid & 31;

#pragma unroll
    for (int it = 0; it < 8; ++it) {
        int idx = tid + it * 256;
        int m   = idx & 63;
        int kg  = idx >> 6;
        int n   = m0 + m;
        float4 v = make_float4(0.f, 0.f, 0.f, 0.f);
        if (n < N_NODES) v = *(const float4*)(x + (size_t)n * H + kg * 4);
        As[(kg * 4 + 0) * 64 + m] = v.x;
        As[(kg * 4 + 1) * 64 + m] = v.y;
        As[(kg * 4 + 2) * 64 + m] = v.z;
        As[(kg * 4 + 3) * 64 + m] = v.w;
    }

    float4 acc[8];
#pragma unroll
    for (int i = 0; i < 8; ++i) acc[i] = make_float4(0.f, 0.f, 0.f, 0.f);

    const float* B = W1 + (size_t)half * 128 * H;

    for (int kc = 0; kc < 4; ++kc) {
        __syncthreads();
#pragma unroll
        for (int it = 0; it < 4; ++it) {
            int idx = tid + it * 256;
            int o4  = idx & 31;
            int r   = idx >> 5;
            *(float4*)(Bs + r * 128 + o4 * 4) =
                *(const float4*)(B + (size_t)(kc * 32 + r) * H + o4 * 4);
        }
        __syncthreads();
#pragma unroll
        for (int k = 0; k < 32; ++k) {
            const float* ap = As + (kc * 32 + k) * 64 + eg * 8;
            float4 a0 = *(const float4*)(ap);
            float4 a1 = *(const float4*)(ap + 4);
            float4 b  = *(const float4*)(Bs + k * 128 + og * 4);
            float ar[8] = {a0.x, a0.y, a0.z, a0.w, a1.x, a1.y, a1.z, a1.w};
#pragma unroll
            for (int i = 0; i < 8; ++i) {
                acc[i].x += ar[i] * b.x;
                acc[i].y += ar[i] * b.y;
                acc[i].z += ar[i] * b.z;
                acc[i].w += ar[i] * b.w;
            }
        }
    }

    float4 bias = make_float4(0.f, 0.f, 0.f, 0.f);
    if (half == 0) bias = *(const float4*)(b1 + og * 4);

#pragma unroll
    for (int i = 0; i < 8; ++i) {
        int n = m0 + eg * 8 + i;
        if (n < N_NODES) {
            float4 v;
            v.x = acc[i].x + bias.x;
            v.y = acc[i].y + bias.y;
            v.z = acc[i].z + bias.z;
            v.w = acc[i].w + bias.w;
            *(float4*)(g_PQ + (size_t)n * 256 + half * 128 + og * 4) = v;
        }
    }
}

// ---------------------------------------------------------------------------
// Edge GEMM (tf32 tensor cores), edges in receiver-sorted (perm) order.
// Epilogue: msg = relu(acc + P[s] + Q[r]) -> plain STG into g_msg[slot].
// ---------------------------------------------------------------------------
__global__ __launch_bounds__(256) void edge_kernel(const float* __restrict__ ef,
                                                   const int* __restrict__ senders,
                                                   const int* __restrict__ receivers,
                                                   const float* __restrict__ W1) {
    extern __shared__ float smem_dyn[];
    float* As = smem_dyn;                       // [64][AS_STRIDE]
    float* Bs = smem_dyn + 64 * AS_STRIDE;      // [128][BS_STRIDE]
    __shared__ int sperm[64];

    const int tid = threadIdx.x;
    const int e0  = blockIdx.x * 64;

    if (tid < 64) sperm[tid] = g_perm[e0 + tid];
    __syncthreads();

    // Load A tile: gathered edge_feat rows, rounded to tf32
#pragma unroll
    for (int it = 0; it < 8; ++it) {
        int idx = tid + it * 256;
        int e   = idx >> 5;
        int kg  = idx & 31;
        float4 v = *(const float4*)(ef + (size_t)sperm[e] * H + kg * 4);
        v.x = tf32r(v.x); v.y = tf32r(v.y); v.z = tf32r(v.z); v.w = tf32r(v.w);
        *(float4*)(As + e * AS_STRIDE + kg * 4) = v;
    }

    // Load B tile (We = rows 256..383 of W1)
    const float* B = W1 + (size_t)256 * H;
#pragma unroll
    for (int it = 0; it < 16; ++it) {
        int idx = tid + it * 256;
        int k   = idx >> 5;
        int o4  = idx & 31;
        float4 v = *(const float4*)(B + (size_t)k * H + o4 * 4);
        v.x = tf32r(v.x); v.y = tf32r(v.y); v.z = tf32r(v.z); v.w = tf32r(v.w);
        *(float4*)(Bs + k * BS_STRIDE + o4 * 4) = v;
    }
    __syncthreads();

    const int lane = tid & 31;
    const int wid  = tid >> 5;
    const int g    = lane >> 2;
    const int tig  = lane & 3;
    const int m_base = (wid & 3) * 16;
    const int n_base = (wid >> 2) * 64;

    float d[8][4];
#pragma unroll
    for (int j = 0; j < 8; ++j)
#pragma unroll
        for (int i = 0; i < 4; ++i) d[j][i] = 0.f;

#pragma unroll
    for (int ks = 0; ks < 16; ++ks) {
        const int k0 = ks * 8;
        const float* ar = As + (m_base + g) * AS_STRIDE + k0 + tig;
        uint32_t a0 = __float_as_uint(ar[0]);
        uint32_t a2 = __float_as_uint(ar[4]);
        uint32_t a1 = __float_as_uint(ar[8 * AS_STRIDE]);
        uint32_t a3 = __float_as_uint(ar[8 * AS_STRIDE + 4]);
        const float* br = Bs + (k0 + tig) * BS_STRIDE + n_base + g;
#pragma unroll
        for (int j = 0; j < 8; ++j) {
            uint32_t b0 = __float_as_uint(br[j * 8]);
            uint32_t b1 = __float_as_uint(br[4 * BS_STRIDE + j * 8]);
            mma_tf32(d[j], a0, a1, a2, a3, b0, b1);
        }
    }

    __syncthreads();

    // Stage accumulators to SMEM for a coalesced epilogue
    float* Cs = smem_dyn;
#pragma unroll
    for (int j = 0; j < 8; ++j) {
        int c = n_base + j * 8 + 2 * tig;
        *(float2*)(Cs + (m_base + g) * AS_STRIDE + c)     = make_float2(d[j][0], d[j][1]);
        *(float2*)(Cs + (m_base + g + 8) * AS_STRIDE + c) = make_float2(d[j][2], d[j][3]);
    }
    __syncthreads();

    // Epilogue: gather P[s], Q[r], relu, store message to its sorted slot
    const int eg = tid >> 5;
    const int og = tid & 31;
#pragma unroll
    for (int i = 0; i < 8; ++i) {
        int el = eg * 8 + i;
        int e  = sperm[el];
        int s  = senders[e];
        int r  = receivers[e];
        float4 m = *(const float4*)(Cs + el * AS_STRIDE + og * 4);
        float4 p = *(const float4*)(g_PQ + (size_t)s * 256 + og * 4);
        float4 q = *(const float4*)(g_PQ + (size_t)r * 256 + 128 + og * 4);
        m.x = fmaxf(m.x + p.x + q.x, 0.f);
        m.y = fmaxf(m.y + p.y + q.y, 0.f);
        m.z = fmaxf(m.z + p.z + q.z, 0.f);
        m.w = fmaxf(m.w + p.w + q.w, 0.f);
        *(float4*)(g_msg + (size_t)(e0 + el) * H + og * 4) = m;
    }
}

// ---------------------------------------------------------------------------
// Fused segment-reduce + residual + LayerNorm. One warp per node.
// ---------------------------------------------------------------------------
__global__ __launch_bounds__(256) void reduce_ln_kernel(const float* __restrict__ x,
                                                        const float* __restrict__ gamma,
                                                        const float* __restrict__ beta,
                                                        float* __restrict__ out) {
    const int warp = threadIdx.x >> 5;
    const int lane = threadIdx.x & 31;
    const int node = blockIdx.x * 8 + warp;
    if (node >= N_NODES) return;

    const int start = g_off[node];
    const int cnt   = g_count[node];

    float4 acc = *(const float4*)(x + (size_t)node * H + lane * 4);
    const float* mp = g_msg + (size_t)start * H + lane * 4;

    int i = 0;
    for (; i + 4 <= cnt; i += 4) {
        float4 m0 = *(const float4*)(mp + (size_t)(i + 0) * H);
        float4 m1 = *(const float4*)(mp + (size_t)(i + 1) * H);
        float4 m2 = *(const float4*)(mp + (size_t)(i + 2) * H);
        float4 m3 = *(const float4*)(mp + (size_t)(i + 3) * H);
        acc.x += (m0.x + m1.x) + (m2.x + m3.x);
        acc.y += (m0.y + m1.y) + (m2.y + m3.y);
        acc.z += (m0.z + m1.z) + (m2.z + m3.z);
        acc.w += (m0.w + m1.w) + (m2.w + m3.w);
    }
    for (; i < cnt; ++i) {
        float4 m = *(const float4*)(mp + (size_t)i * H);
        acc.x += m.x; acc.y += m.y; acc.z += m.z; acc.w += m.w;
    }

    float s  = acc.x + acc.y + acc.z + acc.w;
    float s2 = acc.x * acc.x + acc.y * acc.y + acc.z * acc.z + acc.w * acc.w;
#pragma unroll
    for (int off = 16; off > 0; off >>= 1) {
        s  += __shfl_xor_sync(0xffffffffu, s, off);
        s2 += __shfl_xor_sync(0xffffffffu, s2, off);
    }
    float mean = s * (1.f / H);
    float var  = s2 * (1.f / H) - mean * mean;
    float rstd = rsqrtf(var + LN_EPS);

    float4 g = *(const float4*)(gamma + lane * 4);
    float4 b = *(const float4*)(beta + lane * 4);
    float4 o;
    o.x = g.x * (acc.x - mean) * rstd + b.x;
    o.y = g.y * (acc.y - mean) * rstd + b.y;
    o.z = g.z * (acc.z - mean) * rstd + b.z;
    o.w = g.w * (acc.w - mean) * rstd + b.w;
    *(float4*)(out + (size_t)node * H + lane * 4) = o;
}

// ---------------------------------------------------------------------------
extern "C" void kernel_launch(void* const* d_in, const int* in_sizes, int n_in,
                              void* d_out, int out_size) {
    const float* x         = (const float*)d_in[0];
    const int*   senders   = (const int*)d_in[1];
    const int*   receivers = (const int*)d_in[2];
    const float* ef        = (const float*)d_in[3];
    const float* W1        = (const float*)d_in[4];
    const float* b1        = (const float*)d_in[5];
    const float* gamma     = (const float*)d_in[6];
    const float* beta      = (const float*)d_in[7];
    float*       out       = (float*)d_out;

    cudaFuncSetAttribute(edge_kernel, cudaFuncAttributeMaxDynamicSharedMemorySize,
                         SMEM_EDGE);

    zero_count_kernel<<<(N_NODES + 255) / 256, 256>>>();
    hist_kernel<<<(N_EDGES + 255) / 256, 256>>>(receivers);
    scan_kernel<<<1, 1024>>>();
    scatter_kernel<<<(N_EDGES + 255) / 256, 256>>>(receivers);
    proj_kernel<<<dim3((N_NODES + 63) / 64, 2), 256>>>(x, W1, b1);
    edge_kernel<<<N_EDGES / 64, 256, SMEM_EDGE>>>(ef, senders, receivers, W1);
    reduce_ln_kernel<<<(N_NODES + 7) / 8, 256>>>(x, gamma, beta, out);
}

// round 6
// speedup vs baseline: 2.3406x; 2.3406x over previous
#include <cuda_runtime.h>
#include <cuda_fp16.h>
#include <math.h>
#include <stdint.h>

#define N_NODES 50000
#define N_EDGES 800000
#define H 128
#define LN_EPS 1e-5f

#define AS2_STRIDE 68    // half2 units per A row (64 data + 4 pad)
#define BS2_STRIDE 136   // half2 units per B k-pair row (128 data + 8 pad)
#define CS_STRIDE  132   // float units per C row in epilogue staging
#define SMEM_A2 (64 * AS2_STRIDE * 4)            // 17408 B
#define SMEM_B2 (64 * BS2_STRIDE * 4)            // 34816 B
#define SMEM_EDGE (SMEM_A2 + SMEM_B2)            // 52224 B

// Scratch: per-node projections. [node][256]: 0..127 = P = x@Ws + b1, 128..255 = Q = x@Wr.
__device__ float g_PQ[(size_t)N_NODES * 256];

// Pack two floats into a f16x2 register: lo half = a, hi half = b.
__device__ __forceinline__ uint32_t pack_h2(float a, float b) {
    uint32_t u;
    asm("cvt.rn.f16x2.f32 %0, %1, %2;" : "=r"(u) : "f"(b), "f"(a));
    return u;
}

__device__ __forceinline__ void mma_f16(float d[4], uint32_t a0, uint32_t a1,
                                        uint32_t a2, uint32_t a3,
                                        uint32_t b0, uint32_t b1) {
    asm volatile(
        "mma.sync.aligned.m16n8k16.row.col.f32.f16.f16.f32 "
        "{%0,%1,%2,%3}, {%4,%5,%6,%7}, {%8,%9}, {%0,%1,%2,%3};"
        : "+f"(d[0]), "+f"(d[1]), "+f"(d[2]), "+f"(d[3])
        : "r"(a0), "r"(a1), "r"(a2), "r"(a3), "r"(b0), "r"(b1));
}

// ---------------------------------------------------------------------------
// Kernel 1: node projection (fp32; only 3.3 GFLOP).
// blockIdx.y = 0 -> P = x@Ws + b1, 1 -> Q = x@Wr.
// ---------------------------------------------------------------------------
__global__ __launch_bounds__(256) void proj_kernel(const float* __restrict__ x,
                                                   const float* __restrict__ W1,
                                                   const float* __restrict__ b1) {
    __shared__ float As[128 * 64];
    __shared__ float Bs[32 * 128];

    const int tid  = threadIdx.x;
    const int half = blockIdx.y;
    const int m0   = blockIdx.x * 64;
    const int eg   = tid >> 5;
    const int og   = tid & 31;

#pragma unroll
    for (int it = 0; it < 8; ++it) {
        int idx = tid + it * 256;
        int m   = idx & 63;
        int kg  = idx >> 6;
        int n   = m0 + m;
        float4 v = make_float4(0.f, 0.f, 0.f, 0.f);
        if (n < N_NODES) v = *(const float4*)(x + (size_t)n * H + kg * 4);
        As[(kg * 4 + 0) * 64 + m] = v.x;
        As[(kg * 4 + 1) * 64 + m] = v.y;
        As[(kg * 4 + 2) * 64 + m] = v.z;
        As[(kg * 4 + 3) * 64 + m] = v.w;
    }

    float4 acc[8];
#pragma unroll
    for (int i = 0; i < 8; ++i) acc[i] = make_float4(0.f, 0.f, 0.f, 0.f);

    const float* B = W1 + (size_t)half * 128 * H;

    for (int kc = 0; kc < 4; ++kc) {
        __syncthreads();
#pragma unroll
        for (int it = 0; it < 4; ++it) {
            int idx = tid + it * 256;
            int o4  = idx & 31;
            int r   = idx >> 5;
            *(float4*)(Bs + r * 128 + o4 * 4) =
                *(const float4*)(B + (size_t)(kc * 32 + r) * H + o4 * 4);
        }
        __syncthreads();
#pragma unroll
        for (int k = 0; k < 32; ++k) {
            const float* ap = As + (kc * 32 + k) * 64 + eg * 8;
            float4 a0 = *(const float4*)(ap);
            float4 a1 = *(const float4*)(ap + 4);
            float4 b  = *(const float4*)(Bs + k * 128 + og * 4);
            float ar[8] = {a0.x, a0.y, a0.z, a0.w, a1.x, a1.y, a1.z, a1.w};
#pragma unroll
            for (int i = 0; i < 8; ++i) {
                acc[i].x += ar[i] * b.x;
                acc[i].y += ar[i] * b.y;
                acc[i].z += ar[i] * b.z;
                acc[i].w += ar[i] * b.w;
            }
        }
    }

    float4 bias = make_float4(0.f, 0.f, 0.f, 0.f);
    if (half == 0) bias = *(const float4*)(b1 + og * 4);

#pragma unroll
    for (int i = 0; i < 8; ++i) {
        int n = m0 + eg * 8 + i;
        if (n < N_NODES) {
            float4 v;
            v.x = acc[i].x + bias.x;
            v.y = acc[i].y + bias.y;
            v.z = acc[i].z + bias.z;
            v.w = acc[i].w + bias.w;
            *(float4*)(g_PQ + (size_t)n * 256 + half * 128 + og * 4) = v;
        }
    }
}

// ---------------------------------------------------------------------------
// Kernel 2: out = x (residual preload; edge atomics accumulate into out)
// ---------------------------------------------------------------------------
__global__ void init_kernel(float* __restrict__ out, const float* __restrict__ x) {
    int i = blockIdx.x * blockDim.x + threadIdx.x;
    if (i < N_NODES * H / 4) ((float4*)out)[i] = ((const float4*)x)[i];
}

// ---------------------------------------------------------------------------
// Kernel 3: edge GEMM on fp16 tensor cores (mma.m16n8k16, fp32 accumulate).
// Block tile 64 edges x 128 out, K=128 SMEM-resident as half2 k-pairs.
// 8 warps: 4 (m, 16 rows) x 2 (n, 64 cols).
// Epilogue: stage accum -> SMEM, gather P[s]/Q[r] (fp32), relu, red.v4.
// ---------------------------------------------------------------------------
__global__ __launch_bounds__(256) void edge_kernel(const float* __restrict__ ef,
                                                   const int* __restrict__ senders,
                                                   const int* __restrict__ receivers,
                                                   const float* __restrict__ W1,
                                                   float* __restrict__ out) {
    extern __shared__ float smem_dyn[];
    uint32_t* As2 = (uint32_t*)smem_dyn;                      // [64][AS2_STRIDE] half2: A[e][2k,2k+1]
    uint32_t* Bs2 = (uint32_t*)smem_dyn + 64 * AS2_STRIDE;    // [64][BS2_STRIDE] half2: (B[2k][n], B[2k+1][n])

    const int tid = threadIdx.x;
    const int e0  = blockIdx.x * 64;

    // Load A tile (edge_feat rows e0..e0+63), convert to half2 k-pairs
#pragma unroll
    for (int it = 0; it < 8; ++it) {
        int idx = tid + it * 256;
        int e   = idx >> 5;          // 0..63
        int kg  = idx & 31;          // float4 group: k = 4*kg..4*kg+3
        float4 v = *(const float4*)(ef + (size_t)(e0 + e) * H + kg * 4);
        uint32_t* dst = As2 + e * AS2_STRIDE + kg * 2;
        dst[0] = pack_h2(v.x, v.y);  // k pair (4kg, 4kg+1)
        dst[1] = pack_h2(v.z, v.w);  // k pair (4kg+2, 4kg+3)
    }

    // Load B tile (We = rows 256..383 of W1), as half2 (k even, k odd) per n
    const float* B = W1 + (size_t)256 * H;
#pragma unroll
    for (int it = 0; it < 8; ++it) {
        int idx = tid + it * 256;
        int kp  = idx >> 5;          // k-pair 0..63
        int o4  = idx & 31;          // n group: n = 4*o4..+3
        float4 ve = *(const float4*)(B + (size_t)(2 * kp)     * H + o4 * 4);
        float4 vo = *(const float4*)(B + (size_t)(2 * kp + 1) * H + o4 * 4);
        uint32_t* dst = Bs2 + kp * BS2_STRIDE + o4 * 4;
        dst[0] = pack_h2(ve.x, vo.x);
        dst[1] = pack_h2(ve.y, vo.y);
        dst[2] = pack_h2(ve.z, vo.z);
        dst[3] = pack_h2(ve.w, vo.w);
    }
    __syncthreads();

    const int lane = tid & 31;
    const int wid  = tid >> 5;
    const int g    = lane >> 2;
    const int tig  = lane & 3;
    const int m_base = (wid & 3) * 16;
    const int n_base = (wid >> 2) * 64;

    float d[8][4];
#pragma unroll
    for (int j = 0; j < 8; ++j)
#pragma unroll
        for (int i = 0; i < 4; ++i) d[j][i] = 0.f;

#pragma unroll
    for (int ks = 0; ks < 8; ++ks) {             // K = 8 steps x 16
        const int kp0 = ks * 8;                  // half2 index base
        const uint32_t* ar = As2 + (m_base + g) * AS2_STRIDE + kp0 + tig;
        uint32_t a0 = ar[0];                     // (row g,   k=2tig,2tig+1)
        uint32_t a2 = ar[4];                     // (row g,   k=2tig+8,+9)
        uint32_t a1 = ar[8 * AS2_STRIDE];        // (row g+8, k=2tig..)
        uint32_t a3 = ar[8 * AS2_STRIDE + 4];    // (row g+8, k=2tig+8..)
        const uint32_t* br = Bs2 + (kp0 + tig) * BS2_STRIDE + n_base + g;
#pragma unroll
        for (int j = 0; j < 8; ++j) {
            uint32_t b0 = br[j * 8];                     // (k=2tig..,   n)
            uint32_t b1 = br[4 * BS2_STRIDE + j * 8];    // (k=2tig+8.., n)
            mma_f16(d[j], a0, a1, a2, a3, b0, b1);
        }
    }

    __syncthreads();  // done reading A/B; reuse smem for C staging

    float* Cs = smem_dyn;   // [64][CS_STRIDE]
#pragma unroll
    for (int j = 0; j < 8; ++j) {
        int c = n_base + j * 8 + 2 * tig;
        *(float2*)(Cs + (m_base + g) * CS_STRIDE + c)     = make_float2(d[j][0], d[j][1]);
        *(float2*)(Cs + (m_base + g + 8) * CS_STRIDE + c) = make_float2(d[j][2], d[j][3]);
    }
    __syncthreads();

    // Epilogue: msg = relu(Cs + P[s] + Q[r]); vector-atomic scatter into out[r]
    const int eg = tid >> 5;
    const int og = tid & 31;
#pragma unroll
    for (int i = 0; i < 8; ++i) {
        int el = eg * 8 + i;
        int e  = e0 + el;
        int s  = senders[e];
        int r  = receivers[e];
        float4 m = *(const float4*)(Cs + el * CS_STRIDE + og * 4);
        float4 p = *(const float4*)(g_PQ + (size_t)s * 256 + og * 4);
        float4 q = *(const float4*)(g_PQ + (size_t)r * 256 + 128 + og * 4);
        m.x = fmaxf(m.x + p.x + q.x, 0.f);
        m.y = fmaxf(m.y + p.y + q.y, 0.f);
        m.z = fmaxf(m.z + p.z + q.z, 0.f);
        m.w = fmaxf(m.w + p.w + q.w, 0.f);
        float* dst = out + (size_t)r * H + og * 4;
        asm volatile("red.global.add.v4.f32 [%0], {%1,%2,%3,%4};"
                     :: "l"(dst), "f"(m.x), "f"(m.y), "f"(m.z), "f"(m.w)
                     : "memory");
    }
}

// ---------------------------------------------------------------------------
// Kernel 4: in-place LayerNorm, one warp per row
// ---------------------------------------------------------------------------
__global__ __launch_bounds__(256) void ln_kernel(float* __restrict__ out,
                                                 const float* __restrict__ gamma,
                                                 const float* __restrict__ beta) {
    int warp = threadIdx.x >> 5;
    int lane = threadIdx.x & 31;
    int row  = blockIdx.x * 8 + warp;
    if (row >= N_NODES) return;

    float4 h = *(const float4*)(out + (size_t)row * H + lane * 4);
    float s  = h.x + h.y + h.z + h.w;
    float s2 = h.x * h.x + h.y * h.y + h.z * h.z + h.w * h.w;
#pragma unroll
    for (int off = 16; off > 0; off >>= 1) {
        s  += __shfl_xor_sync(0xffffffffu, s, off);
        s2 += __shfl_xor_sync(0xffffffffu, s2, off);
    }
    float mean = s * (1.f / H);
    float var  = s2 * (1.f / H) - mean * mean;
    float rstd = rsqrtf(var + LN_EPS);

    float4 g = *(const float4*)(gamma + lane * 4);
    float4 b = *(const float4*)(beta + lane * 4);
    float4 o;
    o.x = g.x * (h.x - mean) * rstd + b.x;
    o.y = g.y * (h.y - mean) * rstd + b.y;
    o.z = g.z * (h.z - mean) * rstd + b.z;
    o.w = g.w * (h.w - mean) * rstd + b.w;
    *(float4*)(out + (size_t)row * H + lane * 4) = o;
}

// ---------------------------------------------------------------------------
extern "C" void kernel_launch(void* const* d_in, const int* in_sizes, int n_in,
                              void* d_out, int out_size) {
    const float* x         = (const float*)d_in[0];
    const int*   senders   = (const int*)d_in[1];
    const int*   receivers = (const int*)d_in[2];
    const float* ef        = (const float*)d_in[3];
    const float* W1        = (const float*)d_in[4];
    const float* b1        = (const float*)d_in[5];
    const float* gamma     = (const float*)d_in[6];
    const float* beta      = (const float*)d_in[7];
    float*       out       = (float*)d_out;

    cudaFuncSetAttribute(edge_kernel, cudaFuncAttributeMaxDynamicSharedMemorySize,
                         SMEM_EDGE);

    proj_kernel<<<dim3((N_NODES + 63) / 64, 2), 256>>>(x, W1, b1);
    init_kernel<<<(N_NODES * H / 4 + 255) / 256, 256>>>(out, x);
    edge_kernel<<<N_EDGES / 64, 256, SMEM_EDGE>>>(ef, senders, receivers, W1, out);
    ln_kernel<<<N_NODES / 8, 256>>>(out, gamma, beta);
}